// round 2
// baseline (speedup 1.0000x reference)
#include <cuda_runtime.h>
#include <math.h>

#define B_  8
#define T_  2048
#define E_  1024
#define H_  128
#define BT_ (B_*T_)

// scratch for q, k, v projections (allocation-free: __device__ globals)
__device__ float g_q[BT_*H_];
__device__ float g_k[BT_*H_];
__device__ float g_v[BT_*H_];

// ---------------------------------------------------------------------------
// Projection: out[m, :] = x[m, :] @ W   (M=16384, K=1024, N=128)
// 64x128 output tile per CTA, 256 threads, 4x8 register tile per thread.
// blockIdx.y selects Wq / Wk / Wv.
// ---------------------------------------------------------------------------
__global__ __launch_bounds__(256) void proj_kernel(
    const float* __restrict__ x,  const float* __restrict__ Wq,
    const float* __restrict__ Wk, const float* __restrict__ Wv)
{
    __shared__ float Ast[32][68];   // x tile transposed: [k][row]
    __shared__ float Bs [32][132];  // W tile natural:    [k][col]

    const int m0 = blockIdx.x * 64;
    const float* __restrict__ W =
        (blockIdx.y == 0) ? Wq : (blockIdx.y == 1) ? Wk : Wv;
    float* outp =
        (blockIdx.y == 0) ? g_q : (blockIdx.y == 1) ? g_k : g_v;

    const int t  = threadIdx.x;
    const int ty = t >> 4;   // 0..15 -> rows ty*4..ty*4+3
    const int tx = t & 15;   // 0..15 -> cols tx*8..tx*8+7

    float acc[4][8];
#pragma unroll
    for (int i = 0; i < 4; i++)
#pragma unroll
        for (int j = 0; j < 8; j++) acc[i][j] = 0.f;

    const int ar = t >> 2;   // 0..63  A loader row
    const int ac = t & 3;    // 0..3   A loader f4-col
    const int br = t >> 3;   // 0..31  B loader row
    const int bc = t & 7;    // 0..7   B loader f4-col

    for (int k0 = 0; k0 < E_; k0 += 32) {
        __syncthreads();
        // A: 64 rows x 32 cols of x, stored transposed
#pragma unroll
        for (int p = 0; p < 2; p++) {
            int c4 = ac + p * 4;  // 0..7
            float4 v = *(const float4*)&x[(size_t)(m0 + ar) * E_ + k0 + c4 * 4];
            Ast[c4*4+0][ar] = v.x;
            Ast[c4*4+1][ar] = v.y;
            Ast[c4*4+2][ar] = v.z;
            Ast[c4*4+3][ar] = v.w;
        }
        // B: 32 rows x 128 cols of W, natural layout
#pragma unroll
        for (int p = 0; p < 4; p++) {
            int c4 = bc + p * 8;  // 0..31
            float4 v = *(const float4*)&W[(size_t)(k0 + br) * H_ + c4 * 4];
            *(float4*)&Bs[br][c4 * 4] = v;
        }
        __syncthreads();

#pragma unroll
        for (int kk = 0; kk < 32; kk++) {
            float4 a  = *(const float4*)&Ast[kk][ty * 4];
            float4 b0 = *(const float4*)&Bs[kk][tx * 8];
            float4 b1 = *(const float4*)&Bs[kk][tx * 8 + 4];
            float av[4] = {a.x, a.y, a.z, a.w};
            float bv[8] = {b0.x, b0.y, b0.z, b0.w, b1.x, b1.y, b1.z, b1.w};
#pragma unroll
            for (int i = 0; i < 4; i++)
#pragma unroll
                for (int j = 0; j < 8; j++)
                    acc[i][j] = fmaf(av[i], bv[j], acc[i][j]);
        }
    }

#pragma unroll
    for (int i = 0; i < 4; i++) {
        float4 v0 = {acc[i][0], acc[i][1], acc[i][2], acc[i][3]};
        float4 v1 = {acc[i][4], acc[i][5], acc[i][6], acc[i][7]};
        size_t ro = (size_t)(m0 + ty * 4 + i) * H_ + tx * 8;
        *(float4*)&outp[ro]     = v0;
        *(float4*)&outp[ro + 4] = v1;
    }
}

// ---------------------------------------------------------------------------
// Flash attention (fp32, causal). One CTA = 64 query rows of one batch.
// 256 threads: thread (ty=t/16, tx=t%16).
//   S phase : thread owns S[ty*4+i][tx*4+j]   (64x64 tile)
//   PV phase: thread owns O[ty*4+i][tx*8+j]   (64x128 tile)
// Row stats (m, l) reduced across the 16 tx lanes (half-warp shfl).
// ---------------------------------------------------------------------------
__global__ __launch_bounds__(256, 1) void attn_kernel(float* __restrict__ out)
{
    extern __shared__ float sm[];
    float* Qst = sm;                       // [128][68]  Q^T (scaled)
    float* Kst = Qst + 128 * 68;           // [128][68]  K^T
    float* Vs  = Kst + 128 * 68;           // [64][132]  V natural (k-major)
    float* Pst = Vs  + 64 * 132;           // [64][68]   P^T

    const int qt = (int)gridDim.x - 1 - (int)blockIdx.x;  // longest blocks first
    const int b  = blockIdx.y;
    const int t  = threadIdx.x;
    const int ty = t >> 4;
    const int tx = t & 15;

    const float scale = 45.25483399593904f;  // sqrt(2048)
    const size_t base = (size_t)b * T_ * H_;

    // Load Q tile, transposed + pre-scaled
    {
        const int r  = t >> 2;
        const int c4 = t & 3;
#pragma unroll
        for (int p = 0; p < 8; p++) {
            int cc = (c4 + p * 4) * 4;
            float4 v = *(const float4*)&g_q[base + (size_t)(qt * 64 + r) * H_ + cc];
            Qst[(cc+0)*68 + r] = v.x * scale;
            Qst[(cc+1)*68 + r] = v.y * scale;
            Qst[(cc+2)*68 + r] = v.z * scale;
            Qst[(cc+3)*68 + r] = v.w * scale;
        }
    }

    float o[4][8];
#pragma unroll
    for (int i = 0; i < 4; i++)
#pragma unroll
        for (int j = 0; j < 8; j++) o[i][j] = 0.f;
    float mrow[4], lrow[4];
#pragma unroll
    for (int i = 0; i < 4; i++) { mrow[i] = -INFINITY; lrow[i] = 0.f; }

    for (int kt = 0; kt <= qt; kt++) {
        __syncthreads();  // prior PV done reading Vs/Pst
        // Load K (transposed) and V (natural)
        {
            const int r  = t >> 2;
            const int c4 = t & 3;
#pragma unroll
            for (int p = 0; p < 8; p++) {
                int cc = (c4 + p * 4) * 4;
                float4 v = *(const float4*)&g_k[base + (size_t)(kt * 64 + r) * H_ + cc];
                Kst[(cc+0)*68 + r] = v.x;
                Kst[(cc+1)*68 + r] = v.y;
                Kst[(cc+2)*68 + r] = v.z;
                Kst[(cc+3)*68 + r] = v.w;
            }
            const int vr = t >> 5;   // 0..7
            const int vc = t & 31;   // 0..31 (f4 col)
#pragma unroll
            for (int p = 0; p < 8; p++) {
                int row = vr + p * 8;
                float4 v = *(const float4*)&g_v[base + (size_t)(kt * 64 + row) * H_ + vc * 4];
                *(float4*)&Vs[row * 132 + vc * 4] = v;
            }
        }
        __syncthreads();

        // S = Q K^T (64x64); outer product over head dim
        float s[4][4];
#pragma unroll
        for (int i = 0; i < 4; i++)
#pragma unroll
            for (int j = 0; j < 4; j++) s[i][j] = 0.f;
#pragma unroll 4
        for (int k = 0; k < 128; k++) {
            float4 a  = *(const float4*)&Qst[k * 68 + ty * 4];
            float4 bb = *(const float4*)&Kst[k * 68 + tx * 4];
            float av[4] = {a.x, a.y, a.z, a.w};
            float bv[4] = {bb.x, bb.y, bb.z, bb.w};
#pragma unroll
            for (int i = 0; i < 4; i++)
#pragma unroll
                for (int j = 0; j < 4; j++)
                    s[i][j] = fmaf(av[i], bv[j], s[i][j]);
        }

        if (kt == qt) {  // causal mask only needed on the diagonal tile
#pragma unroll
            for (int i = 0; i < 4; i++) {
                int rg = ty * 4 + i;
#pragma unroll
                for (int j = 0; j < 4; j++)
                    if (tx * 4 + j > rg) s[i][j] = -INFINITY;
            }
        }

        // Online softmax update
        float f[4];
#pragma unroll
        for (int i = 0; i < 4; i++) {
            float v = fmaxf(fmaxf(s[i][0], s[i][1]), fmaxf(s[i][2], s[i][3]));
#pragma unroll
            for (int msk = 1; msk < 16; msk <<= 1)
                v = fmaxf(v, __shfl_xor_sync(0xffffffffu, v, msk));
            float mn = fmaxf(mrow[i], v);
            f[i] = __expf(mrow[i] - mn);
            mrow[i] = mn;
            float rs = 0.f;
#pragma unroll
            for (int j = 0; j < 4; j++) { s[i][j] = __expf(s[i][j] - mn); rs += s[i][j]; }
#pragma unroll
            for (int msk = 1; msk < 16; msk <<= 1)
                rs += __shfl_xor_sync(0xffffffffu, rs, msk);
            lrow[i] = lrow[i] * f[i] + rs;
#pragma unroll
            for (int j = 0; j < 8; j++) o[i][j] *= f[i];
        }

        // Store P transposed: Pst[col][row]
#pragma unroll
        for (int j = 0; j < 4; j++) {
            float4 pv = {s[0][j], s[1][j], s[2][j], s[3][j]};
            *(float4*)&Pst[(tx * 4 + j) * 68 + ty * 4] = pv;
        }
        __syncthreads();

        // O += P V   (outer product over the 64 keys)
#pragma unroll 2
        for (int k = 0; k < 64; k++) {
            float4 a  = *(const float4*)&Pst[k * 68 + ty * 4];
            float4 b0 = *(const float4*)&Vs[k * 132 + tx * 8];
            float4 b1 = *(const float4*)&Vs[k * 132 + tx * 8 + 4];
            float av[4] = {a.x, a.y, a.z, a.w};
            float bv[8] = {b0.x, b0.y, b0.z, b0.w, b1.x, b1.y, b1.z, b1.w};
#pragma unroll
            for (int i = 0; i < 4; i++)
#pragma unroll
                for (int j = 0; j < 8; j++)
                    o[i][j] = fmaf(av[i], bv[j], o[i][j]);
        }
    }

    // Epilogue: normalize and store
#pragma unroll
    for (int i = 0; i < 4; i++) {
        float inv = 1.f / lrow[i];
        float4 v0 = {o[i][0]*inv, o[i][1]*inv, o[i][2]*inv, o[i][3]*inv};
        float4 v1 = {o[i][4]*inv, o[i][5]*inv, o[i][6]*inv, o[i][7]*inv};
        size_t ro = base + (size_t)(qt * 64 + ty * 4 + i) * H_ + tx * 8;
        *(float4*)&out[ro]     = v0;
        *(float4*)&out[ro + 4] = v1;
    }
}

// ---------------------------------------------------------------------------
extern "C" void kernel_launch(void* const* d_in, const int* in_sizes, int n_in,
                              void* d_out, int out_size)
{
    const float* x  = (const float*)d_in[0];
    const float* Wq = (const float*)d_in[1];
    const float* Wk = (const float*)d_in[2];
    const float* Wv = (const float*)d_in[3];
    float* out = (float*)d_out;

    dim3 gp(BT_ / 64, 3);
    proj_kernel<<<gp, 256>>>(x, Wq, Wk, Wv);

    const int smem = (128*68 + 128*68 + 64*132 + 64*68) * 4;  // 120832 B
    cudaFuncSetAttribute(attn_kernel,
                         cudaFuncAttributeMaxDynamicSharedMemorySize, smem);
    dim3 ga(T_ / 64, B_);
    attn_kernel<<<ga, 256, smem>>>(out);
}

// round 4
// speedup vs baseline: 1.8489x; 1.8489x over previous
#include <cuda_runtime.h>
#include <math.h>
#include <cstdint>

#define B_  8
#define T_  2048
#define E_  1024
#define H_  128
#define BT_ (B_*T_)

// scratch (allocation-free: __device__ globals)
__device__ float g_q[BT_*H_];
__device__ float g_k[BT_*H_];
__device__ float g_v[BT_*H_];
__device__ float g_wt[3*H_*E_];   // W^T: [3][128 n][1024 k]

// ---------------------------------------------------------------------------
__device__ __forceinline__ float tf32r(float x) {
    float r; asm("cvt.rna.tf32.f32 %0, %1;" : "=f"(r) : "f"(x)); return r;
}

__device__ __forceinline__ void mma8(float* d, const uint32_t* a, const uint32_t* b) {
    asm volatile(
        "mma.sync.aligned.m16n8k8.row.col.f32.tf32.tf32.f32 "
        "{%0,%1,%2,%3}, {%4,%5,%6,%7}, {%8,%9}, {%0,%1,%2,%3};"
        : "+f"(d[0]), "+f"(d[1]), "+f"(d[2]), "+f"(d[3])
        : "r"(a[0]), "r"(a[1]), "r"(a[2]), "r"(a[3]), "r"(b[0]), "r"(b[1]));
}

// ---------------------------------------------------------------------------
// W transpose: Wt[n][k] = W[k][n]   (1024x128 -> 128x1024), x3 weights
// ---------------------------------------------------------------------------
__global__ void transpose_w(const float* __restrict__ Wq,
                            const float* __restrict__ Wk,
                            const float* __restrict__ Wv)
{
    __shared__ float tile[32][33];
    const int sel = blockIdx.z;
    const float* __restrict__ W = (sel == 0) ? Wq : (sel == 1) ? Wk : Wv;
    float* wt = g_wt + (size_t)sel * H_ * E_;
    const int k0 = blockIdx.x * 32, n0 = blockIdx.y * 32;
    const int tx = threadIdx.x, ty = threadIdx.y;
#pragma unroll
    for (int i = 0; i < 4; i++)
        tile[ty + 8*i][tx] = W[(size_t)(k0 + ty + 8*i) * H_ + n0 + tx];
    __syncthreads();
#pragma unroll
    for (int i = 0; i < 4; i++)
        wt[(size_t)(n0 + ty + 8*i) * E_ + k0 + tx] = tile[tx][ty + 8*i];
}

// ---------------------------------------------------------------------------
// Projection: out = x @ W  via mma.sync tf32, 3xTF32 split.
// CTA 64x128, 8 warps (2m x 4n), warp tile 32x32. K chunks of 32.
// ---------------------------------------------------------------------------
#define PJ_SMEM ((2*64*36 + 2*128*36) * 4)   // 55296 B

__global__ __launch_bounds__(256, 2) void proj_tc(const float* __restrict__ x)
{
    extern __shared__ float sm[];
    float* Ah = sm;                   // [64][36]
    float* Al = Ah + 64*36;
    float* Bh = Al + 64*36;           // [128][36]  (n-major: row n holds 32 k)
    float* Bl = Bh + 128*36;
    const uint32_t* Ahu = (const uint32_t*)Ah;
    const uint32_t* Alu = (const uint32_t*)Al;
    const uint32_t* Bhu = (const uint32_t*)Bh;
    const uint32_t* Blu = (const uint32_t*)Bl;

    const int t    = threadIdx.x;
    const int wid  = t >> 5, lane = t & 31;
    const int wm   = wid >> 2, wn = wid & 3;
    const int g    = lane >> 2, tg = lane & 3;
    const int sel  = blockIdx.y;
    const int m0   = blockIdx.x * 64;

    const float* __restrict__ wt = g_wt + (size_t)sel * (H_ * E_);
    float* outp = (sel == 0) ? g_q : (sel == 1) ? g_k : g_v;

    float acc[2][4][4];
#pragma unroll
    for (int mi = 0; mi < 2; mi++)
#pragma unroll
        for (int ni = 0; ni < 4; ni++)
#pragma unroll
            for (int r = 0; r < 4; r++) acc[mi][ni][r] = 0.f;

    for (int c = 0; c < 32; c++) {
        const int k0 = c * 32;
        __syncthreads();
        // A: x tile 64x32, split hi/lo
#pragma unroll
        for (int p = 0; p < 2; p++) {
            int idx = p * 256 + t;
            int row = idx >> 3, c4 = idx & 7;
            float4 v = *(const float4*)&x[(size_t)(m0 + row) * E_ + k0 + c4 * 4];
            float4 h = {tf32r(v.x), tf32r(v.y), tf32r(v.z), tf32r(v.w)};
            float4 l = {tf32r(v.x - h.x), tf32r(v.y - h.y),
                        tf32r(v.z - h.z), tf32r(v.w - h.w)};
            *(float4*)&Ah[row * 36 + c4 * 4] = h;
            *(float4*)&Al[row * 36 + c4 * 4] = l;
        }
        // B: wt tile 128x32, split hi/lo
#pragma unroll
        for (int p = 0; p < 4; p++) {
            int idx = p * 256 + t;
            int row = idx >> 3, c4 = idx & 7;
            float4 v = *(const float4*)&wt[(size_t)row * E_ + k0 + c4 * 4];
            float4 h = {tf32r(v.x), tf32r(v.y), tf32r(v.z), tf32r(v.w)};
            float4 l = {tf32r(v.x - h.x), tf32r(v.y - h.y),
                        tf32r(v.z - h.z), tf32r(v.w - h.w)};
            *(float4*)&Bh[row * 36 + c4 * 4] = h;
            *(float4*)&Bl[row * 36 + c4 * 4] = l;
        }
        __syncthreads();

#pragma unroll
        for (int ks = 0; ks < 4; ks++) {
            uint32_t ah[2][4], al[2][4];
#pragma unroll
            for (int mi = 0; mi < 2; mi++) {
                int r = wm * 32 + mi * 16 + g;
                int cc = ks * 8 + tg;
                ah[mi][0] = Ahu[r * 36 + cc];
                ah[mi][1] = Ahu[(r + 8) * 36 + cc];
                ah[mi][2] = Ahu[r * 36 + cc + 4];
                ah[mi][3] = Ahu[(r + 8) * 36 + cc + 4];
                al[mi][0] = Alu[r * 36 + cc];
                al[mi][1] = Alu[(r + 8) * 36 + cc];
                al[mi][2] = Alu[r * 36 + cc + 4];
                al[mi][3] = Alu[(r + 8) * 36 + cc + 4];
            }
#pragma unroll
            for (int ni = 0; ni < 4; ni++) {
                int bn = wn * 32 + ni * 8 + g;
                int bk = ks * 8 + tg;
                uint32_t bh[2] = {Bhu[bn * 36 + bk], Bhu[bn * 36 + bk + 4]};
                uint32_t bl[2] = {Blu[bn * 36 + bk], Blu[bn * 36 + bk + 4]};
#pragma unroll
                for (int mi = 0; mi < 2; mi++) {
                    mma8(acc[mi][ni], ah[mi], bh);
                    mma8(acc[mi][ni], ah[mi], bl);
                    mma8(acc[mi][ni], al[mi], bh);
                }
            }
        }
    }

#pragma unroll
    for (int mi = 0; mi < 2; mi++) {
        int row = m0 + wm * 32 + mi * 16 + g;
#pragma unroll
        for (int ni = 0; ni < 4; ni++) {
            int col = wn * 32 + ni * 8 + tg * 2;
            *(float2*)&outp[(size_t)row * H_ + col] =
                make_float2(acc[mi][ni][0], acc[mi][ni][1]);
            *(float2*)&outp[(size_t)(row + 8) * H_ + col] =
                make_float2(acc[mi][ni][2], acc[mi][ni][3]);
        }
    }
}

// ---------------------------------------------------------------------------
// Flash attention via mma.sync tf32.
// BQ=64, BK=32. 8 warps (4m x 2n). QK^T 3xTF32; PV single tf32 (rna-rounded).
// ---------------------------------------------------------------------------
#define AQH 0
#define AQL 8448        // 64*132
#define AKH 16896
#define AKL 21120       // +32*132
#define AVS 25344
#define APS 29696       // +32*136
#define AMX 32000       // +64*36
#define ASU 32128
#define A_SMEM (32256 * 4)   // 129024 B

__global__ __launch_bounds__(256, 1) void attn_tc(float* __restrict__ out)
{
    extern __shared__ float sm[];
    float* Qh = sm + AQH;  float* Ql = sm + AQL;
    float* Kh = sm + AKH;  float* Kl = sm + AKL;
    float* Vs = sm + AVS;  float* Ps = sm + APS;
    float* smax = sm + AMX;  float* ssum = sm + ASU;
    const uint32_t* Qhu = (const uint32_t*)Qh;
    const uint32_t* Qlu = (const uint32_t*)Ql;
    const uint32_t* Khu = (const uint32_t*)Kh;
    const uint32_t* Klu = (const uint32_t*)Kl;
    const uint32_t* Vsu = (const uint32_t*)Vs;
    const uint32_t* Psu = (const uint32_t*)Ps;

    const int t   = threadIdx.x;
    const int wid = t >> 5, lane = t & 31;
    const int wm  = wid >> 1, wn = wid & 1;
    const int g   = lane >> 2, tg = lane & 3;
    const int qt  = (int)gridDim.x - 1 - (int)blockIdx.x;
    const int b   = blockIdx.y;
    const size_t base = (size_t)b * (T_ * H_);
    const float scale = 45.25483399593904f;   // sqrt(2048)

    // Q: 64x128, scaled + split
#pragma unroll
    for (int p = 0; p < 8; p++) {
        int idx = p * 256 + t;
        int row = idx >> 5, c4 = idx & 31;
        float4 v = *(const float4*)&g_q[base + (size_t)(qt * 64 + row) * H_ + c4 * 4];
        v.x *= scale; v.y *= scale; v.z *= scale; v.w *= scale;
        float4 h = {tf32r(v.x), tf32r(v.y), tf32r(v.z), tf32r(v.w)};
        float4 l = {tf32r(v.x - h.x), tf32r(v.y - h.y),
                    tf32r(v.z - h.z), tf32r(v.w - h.w)};
        *(float4*)&Qh[row * 132 + c4 * 4] = h;
        *(float4*)&Ql[row * 132 + c4 * 4] = l;
    }

    float ofrag[8][4];
#pragma unroll
    for (int ni = 0; ni < 8; ni++)
#pragma unroll
        for (int r = 0; r < 4; r++) ofrag[ni][r] = 0.f;
    float mrun[2] = {-INFINITY, -INFINITY};
    float lrun[2] = {0.f, 0.f};

    const int r0 = wm * 16 + g;
    const int r1 = r0 + 8;
    const int ntiles = 2 * qt + 2;

    for (int kt = 0; kt < ntiles; kt++) {
        __syncthreads();
        // K: 32x128 split hi/lo; V: 32x128 tf32-rounded
#pragma unroll
        for (int p = 0; p < 4; p++) {
            int idx = p * 256 + t;
            int row = idx >> 5, c4 = idx & 31;
            float4 v = *(const float4*)&g_k[base + (size_t)(kt * 32 + row) * H_ + c4 * 4];
            float4 h = {tf32r(v.x), tf32r(v.y), tf32r(v.z), tf32r(v.w)};
            float4 l = {tf32r(v.x - h.x), tf32r(v.y - h.y),
                        tf32r(v.z - h.z), tf32r(v.w - h.w)};
            *(float4*)&Kh[row * 132 + c4 * 4] = h;
            *(float4*)&Kl[row * 132 + c4 * 4] = l;

            float4 w = *(const float4*)&g_v[base + (size_t)(kt * 32 + row) * H_ + c4 * 4];
            float4 wh = {tf32r(w.x), tf32r(w.y), tf32r(w.z), tf32r(w.w)};
            *(float4*)&Vs[row * 136 + c4 * 4] = wh;
        }
        __syncthreads();

        // S = Q K^T  (64x32), 3xTF32
        float sfrag[2][4];
#pragma unroll
        for (int ni = 0; ni < 2; ni++)
#pragma unroll
            for (int r = 0; r < 4; r++) sfrag[ni][r] = 0.f;
#pragma unroll 4
        for (int ks = 0; ks < 16; ks++) {
            uint32_t ah[4], al[4];
            int cc = ks * 8 + tg;
            ah[0] = Qhu[r0 * 132 + cc];     ah[1] = Qhu[r1 * 132 + cc];
            ah[2] = Qhu[r0 * 132 + cc + 4]; ah[3] = Qhu[r1 * 132 + cc + 4];
            al[0] = Qlu[r0 * 132 + cc];     al[1] = Qlu[r1 * 132 + cc];
            al[2] = Qlu[r0 * 132 + cc + 4]; al[3] = Qlu[r1 * 132 + cc + 4];
#pragma unroll
            for (int ni = 0; ni < 2; ni++) {
                int bn = wn * 16 + ni * 8 + g;
                uint32_t bh[2] = {Khu[bn * 132 + cc], Khu[bn * 132 + cc + 4]};
                uint32_t bl[2] = {Klu[bn * 132 + cc], Klu[bn * 132 + cc + 4]};
                mma8(sfrag[ni], ah, bh);
                mma8(sfrag[ni], ah, bl);
                mma8(sfrag[ni], al, bh);
            }
        }

        // causal mask (only tiles touching the diagonal)
        if (kt >= 2 * qt) {
            int grow = qt * 64 + wm * 16 + g;
#pragma unroll
            for (int ni = 0; ni < 2; ni++) {
                int col = kt * 32 + wn * 16 + ni * 8 + tg * 2;
                if (col     > grow)     sfrag[ni][0] = -INFINITY;
                if (col + 1 > grow)     sfrag[ni][1] = -INFINITY;
                if (col     > grow + 8) sfrag[ni][2] = -INFINITY;
                if (col + 1 > grow + 8) sfrag[ni][3] = -INFINITY;
            }
        }

        // row max across this warp's 16 cols, then across the 2 n-warps
        float pm0 = fmaxf(fmaxf(sfrag[0][0], sfrag[0][1]),
                          fmaxf(sfrag[1][0], sfrag[1][1]));
        float pm1 = fmaxf(fmaxf(sfrag[0][2], sfrag[0][3]),
                          fmaxf(sfrag[1][2], sfrag[1][3]));
        pm0 = fmaxf(pm0, __shfl_xor_sync(0xffffffffu, pm0, 1));
        pm0 = fmaxf(pm0, __shfl_xor_sync(0xffffffffu, pm0, 2));
        pm1 = fmaxf(pm1, __shfl_xor_sync(0xffffffffu, pm1, 1));
        pm1 = fmaxf(pm1, __shfl_xor_sync(0xffffffffu, pm1, 2));
        if (tg == 0) { smax[wn * 64 + r0] = pm0; smax[wn * 64 + r1] = pm1; }
        __syncthreads();

        float m0n = fmaxf(mrun[0], fmaxf(smax[r0], smax[64 + r0]));
        float m1n = fmaxf(mrun[1], fmaxf(smax[r1], smax[64 + r1]));
        float f0 = __expf(mrun[0] - m0n);
        float f1 = __expf(mrun[1] - m1n);
        mrun[0] = m0n; mrun[1] = m1n;

        // exp, partial sums, write P (tf32-rounded)
        float ps0 = 0.f, ps1 = 0.f;
#pragma unroll
        for (int ni = 0; ni < 2; ni++) {
            float e0 = __expf(sfrag[ni][0] - m0n);
            float e1 = __expf(sfrag[ni][1] - m0n);
            float e2 = __expf(sfrag[ni][2] - m1n);
            float e3 = __expf(sfrag[ni][3] - m1n);
            ps0 += e0 + e1; ps1 += e2 + e3;
            int col = wn * 16 + ni * 8 + tg * 2;
            *(float2*)&Ps[r0 * 36 + col] = make_float2(tf32r(e0), tf32r(e1));
            *(float2*)&Ps[r1 * 36 + col] = make_float2(tf32r(e2), tf32r(e3));
        }
        ps0 += __shfl_xor_sync(0xffffffffu, ps0, 1);
        ps0 += __shfl_xor_sync(0xffffffffu, ps0, 2);
        ps1 += __shfl_xor_sync(0xffffffffu, ps1, 1);
        ps1 += __shfl_xor_sync(0xffffffffu, ps1, 2);
        if (tg == 0) { ssum[wn * 64 + r0] = ps0; ssum[wn * 64 + r1] = ps1; }

        // rescale O
#pragma unroll
        for (int ni = 0; ni < 8; ni++) {
            ofrag[ni][0] *= f0; ofrag[ni][1] *= f0;
            ofrag[ni][2] *= f1; ofrag[ni][3] *= f1;
        }
        __syncthreads();
        lrun[0] = lrun[0] * f0 + ssum[r0] + ssum[64 + r0];
        lrun[1] = lrun[1] * f1 + ssum[r1] + ssum[64 + r1];

        // O += P V  (single tf32)
#pragma unroll
        for (int ks = 0; ks < 4; ks++) {
            uint32_t pa[4];
            int cc = ks * 8 + tg;
            pa[0] = Psu[r0 * 36 + cc];     pa[1] = Psu[r1 * 36 + cc];
            pa[2] = Psu[r0 * 36 + cc + 4]; pa[3] = Psu[r1 * 36 + cc + 4];
#pragma unroll
            for (int ni = 0; ni < 8; ni++) {
                int bn = wn * 64 + ni * 8 + g;
                uint32_t bv[2] = {Vsu[cc * 136 + bn], Vsu[(cc + 4) * 136 + bn]};
                mma8(ofrag[ni], pa, bv);
            }
        }
    }

    // epilogue
    float inv0 = 1.f / lrun[0];
    float inv1 = 1.f / lrun[1];
    int grow = qt * 64 + wm * 16 + g;
#pragma unroll
    for (int ni = 0; ni < 8; ni++) {
        int col = wn * 64 + ni * 8 + tg * 2;
        *(float2*)&out[base + (size_t)grow * H_ + col] =
            make_float2(ofrag[ni][0] * inv0, ofrag[ni][1] * inv0);
        *(float2*)&out[base + (size_t)(grow + 8) * H_ + col] =
            make_float2(ofrag[ni][2] * inv1, ofrag[ni][3] * inv1);
    }
}

// ---------------------------------------------------------------------------
extern "C" void kernel_launch(void* const* d_in, const int* in_sizes, int n_in,
                              void* d_out, int out_size)
{
    const float* x  = (const float*)d_in[0];
    const float* Wq = (const float*)d_in[1];
    const float* Wk = (const float*)d_in[2];
    const float* Wv = (const float*)d_in[3];
    float* out = (float*)d_out;

    transpose_w<<<dim3(E_/32, H_/32, 3), dim3(32, 8)>>>(Wq, Wk, Wv);

    cudaFuncSetAttribute(proj_tc,
                         cudaFuncAttributeMaxDynamicSharedMemorySize, PJ_SMEM);
    proj_tc<<<dim3(BT_/64, 3), 256, PJ_SMEM>>>(x);

    cudaFuncSetAttribute(attn_tc,
                         cudaFuncAttributeMaxDynamicSharedMemorySize, A_SMEM);
    attn_tc<<<dim3(T_/64, B_), 256, A_SMEM>>>(out);
}